// round 10
// baseline (speedup 1.0000x reference)
#include <cuda_runtime.h>
#include <cuda_fp16.h>
#include <cstdint>

#define N_NODES 200000
#define N_EDGES 6400000
#define HIDDEN  200
#define NHID    6
#define TM      64
#define THREADS 256
#define NCTA    ((N_NODES + TM - 1) / TM)   // 3125

#define NKC     14                  // k16 chunks (K=200 padded to 224)
#define NST_L   7                   // stages per layer (2 kc each)
#define NSTAGE  (NHID * NST_L)      // 42
#define KSLAB_B 6400                // bytes per single-kc weight block
#define SLAB_B  (2 * KSLAB_B)       // 12800 per stage
#define ASTRIDE 464                 // bytes per activation row (224 fp16 + pad, conflict-free)

// smem offsets (bytes) — total 74976, 3 CTAs/SM
#define RING_OFF 0                  // 3 x SLAB_B = 38400
#define A_OFF    38400              // 64 x 464 = 29696
#define BIAS_OFF 68096              // 6*200 f32 = 4800
#define WOUT_OFF 72896              // 200 f32 = 800
#define H0_OFF   73696              // 64 f32 = 256
#define ZP_OFF   73952              // 4*64 f32 = 1024
#define SMEM_BYTES 74976

__device__ float g_agg[N_NODES];
__device__ __align__(16) uint2 g_wimg[NHID * NKC * 25 * 32];   // 537600 * 8B

// ---------------- tiny kernels ----------------
__global__ void k_zero() {
    int i = blockIdx.x * blockDim.x + threadIdx.x;
    if (i < N_NODES) g_agg[i] = 0.0f;
}

__global__ void k_scatter(const float* __restrict__ x, const int* __restrict__ ei) {
    int i = blockIdx.x * blockDim.x + threadIdx.x;
    if (i < N_EDGES / 4) {
        const int4 s = reinterpret_cast<const int4*>(ei)[i];
        const int4 d = reinterpret_cast<const int4*>(ei + N_EDGES)[i];
        atomicAdd(&g_agg[d.x], x[s.x]);
        atomicAdd(&g_agg[d.y], x[s.y]);
        atomicAdd(&g_agg[d.z], x[s.z]);
        atomicAdd(&g_agg[d.w], x[s.w]);
    }
}

__device__ __forceinline__ uint32_t packh2(float v0, float v1) {
    __half2 h = __floats2half2_rn(v0, v1);
    return *reinterpret_cast<uint32_t*>(&h);
}

// Pack w_hid into per-lane mma B-fragment order (single fp16):
// idx = ((l*14+kc)*25+nt)*32 + lane -> uint2 {b0, b1}
__global__ void k_prep(const float* __restrict__ w_hid) {
    int idx = blockIdx.x * blockDim.x + threadIdx.x;
    if (idx >= NHID * NKC * 25 * 32) return;
    int lane = idx & 31;
    int u = idx >> 5;
    int nt = u % 25; u /= 25;
    int kc = u % NKC; int l = u / NKC;
    int t = lane & 3, g = lane >> 2;
    int n = nt * 8 + g;
    int k0 = kc * 16 + t * 2;
    float w00 = (k0     < HIDDEN) ? w_hid[((size_t)l * HIDDEN + k0    ) * HIDDEN + n] : 0.f;
    float w01 = (k0 + 1 < HIDDEN) ? w_hid[((size_t)l * HIDDEN + k0 + 1) * HIDDEN + n] : 0.f;
    float w10 = (k0 + 8 < HIDDEN) ? w_hid[((size_t)l * HIDDEN + k0 + 8) * HIDDEN + n] : 0.f;
    float w11 = (k0 + 9 < HIDDEN) ? w_hid[((size_t)l * HIDDEN + k0 + 9) * HIDDEN + n] : 0.f;
    uint2 v;
    v.x = packh2(w00, w01);
    v.y = packh2(w10, w11);
    g_wimg[idx] = v;
}

// ---------------- asm helpers ----------------
__device__ __forceinline__ uint32_t s2u(const void* p) {
    uint32_t a;
    asm("{ .reg .u64 t; cvta.to.shared.u64 t, %1; cvt.u32.u64 %0, t; }" : "=r"(a) : "l"(p));
    return a;
}
__device__ __forceinline__ void cp16(uint32_t sdst, const void* gsrc) {
    asm volatile("cp.async.cg.shared.global [%0], [%1], 16;" :: "r"(sdst), "l"(gsrc));
}
#define CP_COMMIT() asm volatile("cp.async.commit_group;")
#define CP_WAIT1()  asm volatile("cp.async.wait_group 1;")

__device__ __forceinline__ void ldsm4(uint32_t* r, uint32_t a) {
    asm volatile("ldmatrix.sync.aligned.m8n8.x4.shared.b16 {%0,%1,%2,%3}, [%4];"
        : "=r"(r[0]), "=r"(r[1]), "=r"(r[2]), "=r"(r[3]) : "r"(a));
}
__device__ __forceinline__ uint2 lds64(uint32_t a) {
    uint2 v;
    asm volatile("ld.shared.v2.u32 {%0,%1}, [%2];" : "=r"(v.x), "=r"(v.y) : "r"(a));
    return v;
}
__device__ __forceinline__ void sts32(uint32_t a, uint32_t v) {
    asm volatile("st.shared.u32 [%0], %1;" :: "r"(a), "r"(v));
}
__device__ __forceinline__ void mma16816(float* d, const uint32_t* a, uint32_t b0, uint32_t b1) {
    asm volatile("mma.sync.aligned.m16n8k16.row.col.f32.f16.f16.f32 "
        "{%0,%1,%2,%3}, {%4,%5,%6,%7}, {%8,%9}, {%0,%1,%2,%3};"
        : "+f"(d[0]), "+f"(d[1]), "+f"(d[2]), "+f"(d[3])
        : "r"(a[0]), "r"(a[1]), "r"(a[2]), "r"(a[3]), "r"(b0), "r"(b1));
}

// ---------------- layer MMA loop (warp: M=32 rows x NNTW n-tiles) ----------------
// d layout: d[mh*NNTW + nt][4], mh in {0,1} = rows +0..15 / +16..31
template<int NTB, int NNTW>
__device__ __forceinline__ void layer_mmas(
    float (*d)[4], int l, int tid, int lane, uint32_t sb, uint32_t aAddr)
{
    for (int s = 0; s < NST_L; ++s) {
        const int st = l * NST_L + s;
        CP_WAIT1();
        __syncthreads();

        // prefetch stage st+2 (slot (st+2)%3 == (st-1)%3, consumed last iter)
        if (st + 2 < NSTAGE) {
            const char* src = reinterpret_cast<const char*>(g_wimg) + (size_t)(st + 2) * SLAB_B;
            uint32_t dst = sb + RING_OFF + ((st + 2) % 3) * SLAB_B;
            #pragma unroll
            for (int c = 0; c < (SLAB_B / 16 + THREADS - 1) / THREADS; ++c) {
                int idx = tid + c * THREADS;
                if (idx < SLAB_B / 16) cp16(dst + idx * 16, src + idx * 16);
            }
        }
        CP_COMMIT();

        const uint32_t ring = sb + RING_OFF + (st % 3) * SLAB_B;
        #pragma unroll
        for (int kc = 0; kc < 2; ++kc) {
            uint32_t a0[4], a1[4];
            const uint32_t acol = (uint32_t)(s * 2 + kc) * 32;
            ldsm4(a0, aAddr + acol);
            ldsm4(a1, aAddr + 16 * ASTRIDE + acol);

            const uint32_t bbase = ring + kc * KSLAB_B + lane * 8 + NTB * 256;
            #pragma unroll
            for (int nt = 0; nt < NNTW; ++nt) {
                uint2 B = lds64(bbase + nt * 256);
                mma16816(d[nt],        a0, B.x, B.y);
                mma16816(d[NNTW + nt], a1, B.x, B.y);
            }
        }
    }
    __syncthreads();   // all ldsm reads of this layer's A done before epilogue overwrites A
}

template<int NTB, int NNTW>
__device__ __forceinline__ void epi_store(
    const float (*d)[4], const float* biasL, int mg, int g, int t, uint32_t sb)
{
    #pragma unroll
    for (int mh = 0; mh < 2; ++mh) {
        const uint32_t off0 = (uint32_t)(mg * 32 + mh * 16 + g) * ASTRIDE;
        #pragma unroll
        for (int nt = 0; nt < NNTW; ++nt) {
            const float* dd = d[mh * NNTW + nt];
            int c0 = 8 * (NTB + nt) + 2 * t;
            float b0 = biasL[c0], b1 = biasL[c0 + 1];
            float v0 = fmaxf(dd[0] + b0, 0.f), v1 = fmaxf(dd[1] + b1, 0.f);
            float v2 = fmaxf(dd[2] + b0, 0.f), v3 = fmaxf(dd[3] + b1, 0.f);
            uint32_t a0 = off0 + (uint32_t)c0 * 2;
            sts32(sb + A_OFF + a0, packh2(v0, v1));
            sts32(sb + A_OFF + a0 + 8 * ASTRIDE, packh2(v2, v3));
        }
    }
}

template<int NTB, int NNTW>
__device__ __forceinline__ void epi_final(
    const float (*d)[4], const float* biasL, const float* woutS,
    float* zp, int ng, int mg, int g, int t)
{
    #pragma unroll
    for (int mh = 0; mh < 2; ++mh) {
        float z0 = 0.f, z1 = 0.f;
        #pragma unroll
        for (int nt = 0; nt < NNTW; ++nt) {
            const float* dd = d[mh * NNTW + nt];
            int c0 = 8 * (NTB + nt) + 2 * t;
            float b0 = biasL[c0], b1 = biasL[c0 + 1];
            float w0 = woutS[c0], w1 = woutS[c0 + 1];
            z0 = fmaf(fmaxf(dd[0] + b0, 0.f), w0, z0);
            z0 = fmaf(fmaxf(dd[1] + b1, 0.f), w1, z0);
            z1 = fmaf(fmaxf(dd[2] + b0, 0.f), w0, z1);
            z1 = fmaf(fmaxf(dd[3] + b1, 0.f), w1, z1);
        }
        z0 += __shfl_xor_sync(0xffffffffu, z0, 1);
        z0 += __shfl_xor_sync(0xffffffffu, z0, 2);
        z1 += __shfl_xor_sync(0xffffffffu, z1, 1);
        z1 += __shfl_xor_sync(0xffffffffu, z1, 2);
        if (t == 0) {
            int rl = mg * 32 + mh * 16 + g;
            zp[ng * TM + rl]     = z0;
            zp[ng * TM + rl + 8] = z1;
        }
    }
}

// ---------------- fused GraphConv + MLP + sigmoid ----------------
__global__ void __launch_bounds__(THREADS, 3) k_mlp(
    const float* __restrict__ x,
    const float* __restrict__ w_rel, const float* __restrict__ b_rel,
    const float* __restrict__ w_root,
    const float* __restrict__ w_in,  const float* __restrict__ b_in,
    const float* __restrict__ b_hid,
    const float* __restrict__ w_out, const float* __restrict__ b_out,
    float* __restrict__ out)
{
    extern __shared__ char smem[];
    const uint32_t sb = s2u(smem);
    const int tid  = threadIdx.x;
    const int warp = tid >> 5;
    const int lane = tid & 31;
    const int mg   = warp >> 2;        // m-group: rows mg*32 .. mg*32+31
    const int ng   = warp & 3;         // n-group: tiles {0:0-6, 1:7-12, 2:13-18, 3:19-24}
    const int g    = lane >> 2;
    const int t    = lane & 3;
    const int row0 = blockIdx.x * TM;

    float* biasS = reinterpret_cast<float*>(smem + BIAS_OFF);   // [6][200]
    float* woutS = reinterpret_cast<float*>(smem + WOUT_OFF);
    float* h0S   = reinterpret_cast<float*>(smem + H0_OFF);
    float* zp    = reinterpret_cast<float*>(smem + ZP_OFF);     // [4][64]

    // stage small vectors + h0
    if (tid < HIDDEN) woutS[tid] = __ldg(w_out + tid);
    for (int i = tid; i < NHID * HIDDEN; i += THREADS) biasS[i] = __ldg(b_hid + i);
    if (tid < TM) {
        int r = row0 + tid;
        float a  = (r < N_NODES) ? g_agg[r] : 0.0f;
        float xv = (r < N_NODES) ? __ldg(x + r) : 0.0f;
        h0S[tid] = a * __ldg(w_rel) + __ldg(b_rel) + xv * __ldg(w_root);
    }
    __syncthreads();

    // layer-1 activations (rank-1): A[r][k] = relu(h0[r]*w_in[k]+b_in[k]), k>=200 -> 0
    for (int i = tid; i < TM * 224; i += THREADS) {
        int r = i / 224, k = i - r * 224;
        float v = 0.0f;
        if (k < HIDDEN) v = fmaxf(fmaf(h0S[r], __ldg(w_in + k), __ldg(b_in + k)), 0.0f);
        *reinterpret_cast<__half*>(smem + A_OFF + r * ASTRIDE + k * 2) = __float2half_rn(v);
    }

    // prefetch weight stages 0,1
    #pragma unroll
    for (int ps = 0; ps < 2; ++ps) {
        const char* src = reinterpret_cast<const char*>(g_wimg) + (size_t)ps * SLAB_B;
        uint32_t dst = sb + RING_OFF + ps * SLAB_B;
        for (int c = tid; c < SLAB_B / 16; c += THREADS)
            cp16(dst + c * 16, src + c * 16);
        CP_COMMIT();
    }

    // ldmatrix per-lane address (rows mg*32 .. +15; second half at +16*ASTRIDE)
    const int lrow = lane & 15;
    const uint32_t aAddr = sb + A_OFF + (mg * 32 + lrow) * ASTRIDE + (lane >> 4) * 16;

    float d[14][4];   // [2 m-halves][<=7 n-tiles][4]

    for (int l = 0; l < NHID; ++l) {
        #pragma unroll
        for (int q = 0; q < 14; ++q) {
            d[q][0] = 0.f; d[q][1] = 0.f; d[q][2] = 0.f; d[q][3] = 0.f;
        }

        switch (ng) {
            case 0: layer_mmas<0, 7>(d, l, tid, lane, sb, aAddr); break;
            case 1: layer_mmas<7, 6>(d, l, tid, lane, sb, aAddr); break;
            case 2: layer_mmas<13, 6>(d, l, tid, lane, sb, aAddr); break;
            default: layer_mmas<19, 6>(d, l, tid, lane, sb, aAddr); break;
        }

        const float* biasL = biasS + l * HIDDEN;
        if (l < NHID - 1) {
            switch (ng) {
                case 0: epi_store<0, 7>(d, biasL, mg, g, t, sb); break;
                case 1: epi_store<7, 6>(d, biasL, mg, g, t, sb); break;
                case 2: epi_store<13, 6>(d, biasL, mg, g, t, sb); break;
                default: epi_store<19, 6>(d, biasL, mg, g, t, sb); break;
            }
        } else {
            switch (ng) {
                case 0: epi_final<0, 7>(d, biasL, woutS, zp, ng, mg, g, t); break;
                case 1: epi_final<7, 6>(d, biasL, woutS, zp, ng, mg, g, t); break;
                case 2: epi_final<13, 6>(d, biasL, woutS, zp, ng, mg, g, t); break;
                default: epi_final<19, 6>(d, biasL, woutS, zp, ng, mg, g, t); break;
            }
        }
    }

    __syncthreads();
    if (tid < TM) {
        int r = row0 + tid;
        if (r < N_NODES) {
            float z = zp[tid] + zp[TM + tid] + zp[2 * TM + tid] + zp[3 * TM + tid] + __ldg(b_out);
            out[r] = 1.0f / (1.0f + expf(-z));
        }
    }
}

// ---------------- launch ----------------
extern "C" void kernel_launch(void* const* d_in, const int* in_sizes, int n_in,
                              void* d_out, int out_size)
{
    const float* x      = (const float*)d_in[0];
    const int*   ei     = (const int*)d_in[1];      // int32 (jax x64 disabled)
    const float* w_rel  = (const float*)d_in[2];
    const float* b_rel  = (const float*)d_in[3];
    const float* w_root = (const float*)d_in[4];
    const float* w_in   = (const float*)d_in[5];
    const float* b_in   = (const float*)d_in[6];
    const float* w_hid  = (const float*)d_in[7];
    const float* b_hid  = (const float*)d_in[8];
    const float* w_out  = (const float*)d_in[9];
    const float* b_out  = (const float*)d_in[10];
    float*       out    = (float*)d_out;

    cudaFuncSetAttribute(k_mlp, cudaFuncAttributeMaxDynamicSharedMemorySize, SMEM_BYTES);

    k_prep<<<(NHID * NKC * 25 * 32 + 255) / 256, 256>>>(w_hid);
    k_zero<<<(N_NODES + 255) / 256, 256>>>();
    k_scatter<<<(N_EDGES / 4 + 255) / 256, 256>>>(x, ei);
    k_mlp<<<NCTA, THREADS, SMEM_BYTES>>>(
        x, w_rel, b_rel, w_root, w_in, b_in, b_hid, w_out, b_out, out);
}

// round 11
// speedup vs baseline: 1.0969x; 1.0969x over previous
#include <cuda_runtime.h>
#include <cuda_fp16.h>
#include <cstdint>

#define N_NODES 200000
#define N_EDGES 6400000
#define HIDDEN  200
#define NHID    6
#define TM      64
#define THREADS 256
#define NCTA    ((N_NODES + TM - 1) / TM)   // 3125

#define NKC     13                  // k16 chunks (K=200 padded to 208)
#define ASTRIDE 432                 // bytes per activation row (216 fp16, conflict-free)

// smem offsets (bytes) — total 34528
#define A_OFF    0                  // 64 x 432 = 27648
#define BIAS_OFF 27648              // 6*200 f32 = 4800
#define WOUT_OFF 32448              // 200 f32 = 800
#define H0_OFF   33248              // 64 f32 = 256
#define ZP_OFF   33504              // 4*64 f32 = 1024
#define SMEM_BYTES 34528

__device__ float g_agg[N_NODES];
// per-lane packed B fragments: idx = ((l*13+kc)*25+nt)*32 + lane -> uint2 {b0,b1}
__device__ __align__(16) uint2 g_wimg[NHID * NKC * 25 * 32];   // 499200 B (L2-resident)

// ---------------- tiny kernels ----------------
__global__ void k_zero() {
    int i = blockIdx.x * blockDim.x + threadIdx.x;
    if (i < N_NODES) g_agg[i] = 0.0f;
}

__global__ void k_scatter(const float* __restrict__ x, const int* __restrict__ ei) {
    int i = blockIdx.x * blockDim.x + threadIdx.x;
    if (i < N_EDGES / 4) {
        const int4 s = reinterpret_cast<const int4*>(ei)[i];
        const int4 d = reinterpret_cast<const int4*>(ei + N_EDGES)[i];
        atomicAdd(&g_agg[d.x], x[s.x]);
        atomicAdd(&g_agg[d.y], x[s.y]);
        atomicAdd(&g_agg[d.z], x[s.z]);
        atomicAdd(&g_agg[d.w], x[s.w]);
    }
}

__device__ __forceinline__ uint32_t packh2(float v0, float v1) {
    __half2 h = __floats2half2_rn(v0, v1);
    return *reinterpret_cast<uint32_t*>(&h);
}

__global__ void k_prep(const float* __restrict__ w_hid) {
    int idx = blockIdx.x * blockDim.x + threadIdx.x;
    if (idx >= NHID * NKC * 25 * 32) return;
    int lane = idx & 31;
    int u = idx >> 5;
    int nt = u % 25; u /= 25;
    int kc = u % NKC; int l = u / NKC;
    int t = lane & 3, g = lane >> 2;
    int n = nt * 8 + g;
    int k0 = kc * 16 + t * 2;
    float w00 = (k0     < HIDDEN) ? w_hid[((size_t)l * HIDDEN + k0    ) * HIDDEN + n] : 0.f;
    float w01 = (k0 + 1 < HIDDEN) ? w_hid[((size_t)l * HIDDEN + k0 + 1) * HIDDEN + n] : 0.f;
    float w10 = (k0 + 8 < HIDDEN) ? w_hid[((size_t)l * HIDDEN + k0 + 8) * HIDDEN + n] : 0.f;
    float w11 = (k0 + 9 < HIDDEN) ? w_hid[((size_t)l * HIDDEN + k0 + 9) * HIDDEN + n] : 0.f;
    uint2 v;
    v.x = packh2(w00, w01);
    v.y = packh2(w10, w11);
    g_wimg[idx] = v;
}

// ---------------- asm helpers ----------------
__device__ __forceinline__ uint32_t s2u(const void* p) {
    uint32_t a;
    asm("{ .reg .u64 t; cvta.to.shared.u64 t, %1; cvt.u32.u64 %0, t; }" : "=r"(a) : "l"(p));
    return a;
}
__device__ __forceinline__ void ldsm4(uint32_t* r, uint32_t a) {
    asm volatile("ldmatrix.sync.aligned.m8n8.x4.shared.b16 {%0,%1,%2,%3}, [%4];"
        : "=r"(r[0]), "=r"(r[1]), "=r"(r[2]), "=r"(r[3]) : "r"(a));
}
__device__ __forceinline__ void sts32(uint32_t a, uint32_t v) {
    asm volatile("st.shared.u32 [%0], %1;" :: "r"(a), "r"(v));
}
__device__ __forceinline__ void mma16816(float* d, const uint32_t* a, uint32_t b0, uint32_t b1) {
    asm volatile("mma.sync.aligned.m16n8k16.row.col.f32.f16.f16.f32 "
        "{%0,%1,%2,%3}, {%4,%5,%6,%7}, {%8,%9}, {%0,%1,%2,%3};"
        : "+f"(d[0]), "+f"(d[1]), "+f"(d[2]), "+f"(d[3])
        : "r"(a[0]), "r"(a[1]), "r"(a[2]), "r"(a[3]), "r"(b0), "r"(b1));
}

// ---------------- layer MMA loop: warp = M32 x NNTW n8-tiles, B direct from L2 ----------------
// d layout: d[mh*NNTW + nt][4], mh in {0,1}
template<int NTB, int NNTW>
__device__ __forceinline__ void layer_mmas(
    float (*d)[4], const uint2* __restrict__ gwl, uint32_t aAddr)
{
    #pragma unroll
    for (int kc = 0; kc < NKC; ++kc) {
        uint32_t a0[4], a1[4];
        ldsm4(a0, aAddr + kc * 32);
        ldsm4(a1, aAddr + 16 * ASTRIDE + kc * 32);

        const uint2* gk = gwl + (size_t)kc * 800;   // 25 nt * 32 lanes
        uint2 B[NNTW];
        #pragma unroll
        for (int nt = 0; nt < NNTW; ++nt) B[nt] = __ldg(gk + nt * 32);

        #pragma unroll
        for (int nt = 0; nt < NNTW; ++nt) {
            mma16816(d[nt],        a0, B[nt].x, B[nt].y);
            mma16816(d[NNTW + nt], a1, B[nt].x, B[nt].y);
        }
    }
}

template<int NTB, int NNTW>
__device__ __forceinline__ void epi_store(
    const float (*d)[4], const float* biasL, int mg, int g, int t, uint32_t sb)
{
    #pragma unroll
    for (int mh = 0; mh < 2; ++mh) {
        const uint32_t off0 = (uint32_t)(mg * 32 + mh * 16 + g) * ASTRIDE;
        #pragma unroll
        for (int nt = 0; nt < NNTW; ++nt) {
            const float* dd = d[mh * NNTW + nt];
            int c0 = 8 * (NTB + nt) + 2 * t;
            float b0 = biasL[c0], b1 = biasL[c0 + 1];
            float v0 = fmaxf(dd[0] + b0, 0.f), v1 = fmaxf(dd[1] + b1, 0.f);
            float v2 = fmaxf(dd[2] + b0, 0.f), v3 = fmaxf(dd[3] + b1, 0.f);
            uint32_t a0 = off0 + (uint32_t)c0 * 2;
            sts32(sb + A_OFF + a0, packh2(v0, v1));
            sts32(sb + A_OFF + a0 + 8 * ASTRIDE, packh2(v2, v3));
        }
    }
}

template<int NTB, int NNTW>
__device__ __forceinline__ void epi_final(
    const float (*d)[4], const float* biasL, const float* woutS,
    float* zp, int ng, int mg, int g, int t)
{
    #pragma unroll
    for (int mh = 0; mh < 2; ++mh) {
        float z0 = 0.f, z1 = 0.f;
        #pragma unroll
        for (int nt = 0; nt < NNTW; ++nt) {
            const float* dd = d[mh * NNTW + nt];
            int c0 = 8 * (NTB + nt) + 2 * t;
            float b0 = biasL[c0], b1 = biasL[c0 + 1];
            float w0 = woutS[c0], w1 = woutS[c0 + 1];
            z0 = fmaf(fmaxf(dd[0] + b0, 0.f), w0, z0);
            z0 = fmaf(fmaxf(dd[1] + b1, 0.f), w1, z0);
            z1 = fmaf(fmaxf(dd[2] + b0, 0.f), w0, z1);
            z1 = fmaf(fmaxf(dd[3] + b1, 0.f), w1, z1);
        }
        z0 += __shfl_xor_sync(0xffffffffu, z0, 1);
        z0 += __shfl_xor_sync(0xffffffffu, z0, 2);
        z1 += __shfl_xor_sync(0xffffffffu, z1, 1);
        z1 += __shfl_xor_sync(0xffffffffu, z1, 2);
        if (t == 0) {
            int rl = mg * 32 + mh * 16 + g;
            zp[ng * TM + rl]     = z0;
            zp[ng * TM + rl + 8] = z1;
        }
    }
}

// ---------------- fused GraphConv + MLP + sigmoid ----------------
__global__ void __launch_bounds__(THREADS, 2) k_mlp(
    const float* __restrict__ x,
    const float* __restrict__ w_rel, const float* __restrict__ b_rel,
    const float* __restrict__ w_root,
    const float* __restrict__ w_in,  const float* __restrict__ b_in,
    const float* __restrict__ b_hid,
    const float* __restrict__ w_out, const float* __restrict__ b_out,
    float* __restrict__ out)
{
    extern __shared__ char smem[];
    const uint32_t sb = s2u(smem);
    const int tid  = threadIdx.x;
    const int warp = tid >> 5;
    const int lane = tid & 31;
    const int mg   = warp >> 2;        // m-group: rows mg*32 .. +31
    const int ng   = warp & 3;         // n-group: tiles {0:0-6, 1:7-12, 2:13-18, 3:19-24}
    const int g    = lane >> 2;
    const int t    = lane & 3;
    const int row0 = blockIdx.x * TM;

    float* biasS = reinterpret_cast<float*>(smem + BIAS_OFF);   // [6][200]
    float* woutS = reinterpret_cast<float*>(smem + WOUT_OFF);
    float* h0S   = reinterpret_cast<float*>(smem + H0_OFF);
    float* zp    = reinterpret_cast<float*>(smem + ZP_OFF);     // [4][64]

    // stage small vectors + h0
    if (tid < HIDDEN) woutS[tid] = __ldg(w_out + tid);
    for (int i = tid; i < NHID * HIDDEN; i += THREADS) biasS[i] = __ldg(b_hid + i);
    if (tid < TM) {
        int r = row0 + tid;
        float a  = (r < N_NODES) ? g_agg[r] : 0.0f;
        float xv = (r < N_NODES) ? __ldg(x + r) : 0.0f;
        h0S[tid] = a * __ldg(w_rel) + __ldg(b_rel) + xv * __ldg(w_root);
    }
    __syncthreads();

    // layer-1 activations (rank-1): A[r][k] = relu(h0[r]*w_in[k]+b_in[k]), k>=200 -> 0
    for (int i = tid; i < TM * 208; i += THREADS) {
        int r = i / 208, k = i - r * 208;
        float v = 0.0f;
        if (k < HIDDEN) v = fmaxf(fmaf(h0S[r], __ldg(w_in + k), __ldg(b_in + k)), 0.0f);
        *reinterpret_cast<__half*>(smem + A_OFF + r * ASTRIDE + k * 2) = __float2half_rn(v);
    }
    __syncthreads();

    // ldmatrix per-lane address (rows mg*32 .. +15; second half at +16*ASTRIDE)
    const int lrow = lane & 15;
    const uint32_t aAddr = sb + A_OFF + (mg * 32 + lrow) * ASTRIDE + (lane >> 4) * 16;

    // per-warp B base (lane-packed fragments)
    const int NTBv = (ng == 0) ? 0 : (ng == 1) ? 7 : (ng == 2) ? 13 : 19;
    const uint2* gwBase = g_wimg + NTBv * 32 + lane;

    float d[14][4];   // [2 m-halves][<=7 n-tiles][4]

    for (int l = 0; l < NHID; ++l) {
        #pragma unroll
        for (int q = 0; q < 14; ++q) {
            d[q][0] = 0.f; d[q][1] = 0.f; d[q][2] = 0.f; d[q][3] = 0.f;
        }
        const uint2* gwl = gwBase + (size_t)l * NKC * 800;

        switch (ng) {
            case 0: layer_mmas<0, 7>(d, gwl, aAddr); break;
            case 1: layer_mmas<7, 6>(d, gwl, aAddr); break;
            case 2: layer_mmas<13, 6>(d, gwl, aAddr); break;
            default: layer_mmas<19, 6>(d, gwl, aAddr); break;
        }

        const float* biasL = biasS + l * HIDDEN;
        if (l < NHID - 1) {
            __syncthreads();   // all ldsm reads of this layer's A done
            switch (ng) {
                case 0: epi_store<0, 7>(d, biasL, mg, g, t, sb); break;
                case 1: epi_store<7, 6>(d, biasL, mg, g, t, sb); break;
                case 2: epi_store<13, 6>(d, biasL, mg, g, t, sb); break;
                default: epi_store<19, 6>(d, biasL, mg, g, t, sb); break;
            }
            __syncthreads();   // new A visible before next layer's ldsm
        } else {
            switch (ng) {
                case 0: epi_final<0, 7>(d, biasL, woutS, zp, ng, mg, g, t); break;
                case 1: epi_final<7, 6>(d, biasL, woutS, zp, ng, mg, g, t); break;
                case 2: epi_final<13, 6>(d, biasL, woutS, zp, ng, mg, g, t); break;
                default: epi_final<19, 6>(d, biasL, woutS, zp, ng, mg, g, t); break;
            }
        }
    }

    __syncthreads();
    if (tid < TM) {
        int r = row0 + tid;
        if (r < N_NODES) {
            float z = zp[tid] + zp[TM + tid] + zp[2 * TM + tid] + zp[3 * TM + tid] + __ldg(b_out);
            out[r] = 1.0f / (1.0f + expf(-z));
        }
    }
}

// ---------------- launch ----------------
extern "C" void kernel_launch(void* const* d_in, const int* in_sizes, int n_in,
                              void* d_out, int out_size)
{
    const float* x      = (const float*)d_in[0];
    const int*   ei     = (const int*)d_in[1];      // int32 (jax x64 disabled)
    const float* w_rel  = (const float*)d_in[2];
    const float* b_rel  = (const float*)d_in[3];
    const float* w_root = (const float*)d_in[4];
    const float* w_in   = (const float*)d_in[5];
    const float* b_in   = (const float*)d_in[6];
    const float* w_hid  = (const float*)d_in[7];
    const float* b_hid  = (const float*)d_in[8];
    const float* w_out  = (const float*)d_in[9];
    const float* b_out  = (const float*)d_in[10];
    float*       out    = (float*)d_out;

    cudaFuncSetAttribute(k_mlp, cudaFuncAttributeMaxDynamicSharedMemorySize, SMEM_BYTES);

    k_prep<<<(NHID * NKC * 25 * 32 + 255) / 256, 256>>>(w_hid);
    k_zero<<<(N_NODES + 255) / 256, 256>>>();
    k_scatter<<<(N_EDGES / 4 + 255) / 256, 256>>>(x, ei);
    k_mlp<<<NCTA, THREADS, SMEM_BYTES>>>(
        x, w_rel, b_rel, w_root, w_in, b_in, b_hid, w_out, b_out, out);
}

// round 12
// speedup vs baseline: 1.0977x; 1.0008x over previous
#include <cuda_runtime.h>
#include <cuda_fp16.h>
#include <cstdint>

#define N_NODES 200000
#define N_EDGES 6400000
#define HIDDEN  200
#define NHID    6
#define TM      64
#define THREADS 256
#define NCTA    ((N_NODES + TM - 1) / TM)   // 3125

#define NKC     13                  // k16 chunks (K=200 padded to 208)
#define ASTRIDE 432                 // bytes per activation row (216 fp16, conflict-free)

// smem offsets (bytes) — total 34528
#define A_OFF    0                  // 64 x 432 = 27648
#define BIAS_OFF 27648              // 6*200 f32 = 4800
#define WOUT_OFF 32448              // 200 f32 = 800
#define H0_OFF   33248              // 64 f32 = 256
#define ZP_OFF   33504              // 4*64 f32 = 1024
#define SMEM_BYTES 34528

__device__ float g_agg[N_NODES];
// per-lane packed B fragments: idx = ((l*13+kc)*25+nt)*32 + lane -> uint2 {b0,b1}
__device__ __align__(16) uint2 g_wimg[NHID * NKC * 25 * 32];   // 499200 B (L2-resident)

// ---------------- tiny kernels ----------------
__global__ void k_zero() {
    int i = blockIdx.x * blockDim.x + threadIdx.x;
    if (i < N_NODES) g_agg[i] = 0.0f;
}

__global__ void k_scatter(const float* __restrict__ x, const int* __restrict__ ei) {
    int i = blockIdx.x * blockDim.x + threadIdx.x;
    if (i < N_EDGES / 4) {
        const int4 s = reinterpret_cast<const int4*>(ei)[i];
        const int4 d = reinterpret_cast<const int4*>(ei + N_EDGES)[i];
        atomicAdd(&g_agg[d.x], x[s.x]);
        atomicAdd(&g_agg[d.y], x[s.y]);
        atomicAdd(&g_agg[d.z], x[s.z]);
        atomicAdd(&g_agg[d.w], x[s.w]);
    }
}

__device__ __forceinline__ uint32_t packh2(float v0, float v1) {
    __half2 h = __floats2half2_rn(v0, v1);
    return *reinterpret_cast<uint32_t*>(&h);
}

__global__ void k_prep(const float* __restrict__ w_hid) {
    int idx = blockIdx.x * blockDim.x + threadIdx.x;
    if (idx >= NHID * NKC * 25 * 32) return;
    int lane = idx & 31;
    int u = idx >> 5;
    int nt = u % 25; u /= 25;
    int kc = u % NKC; int l = u / NKC;
    int t = lane & 3, g = lane >> 2;
    int n = nt * 8 + g;
    int k0 = kc * 16 + t * 2;
    float w00 = (k0     < HIDDEN) ? w_hid[((size_t)l * HIDDEN + k0    ) * HIDDEN + n] : 0.f;
    float w01 = (k0 + 1 < HIDDEN) ? w_hid[((size_t)l * HIDDEN + k0 + 1) * HIDDEN + n] : 0.f;
    float w10 = (k0 + 8 < HIDDEN) ? w_hid[((size_t)l * HIDDEN + k0 + 8) * HIDDEN + n] : 0.f;
    float w11 = (k0 + 9 < HIDDEN) ? w_hid[((size_t)l * HIDDEN + k0 + 9) * HIDDEN + n] : 0.f;
    uint2 v;
    v.x = packh2(w00, w01);
    v.y = packh2(w10, w11);
    g_wimg[idx] = v;
}

// ---------------- asm helpers ----------------
__device__ __forceinline__ uint32_t s2u(const void* p) {
    uint32_t a;
    asm("{ .reg .u64 t; cvta.to.shared.u64 t, %1; cvt.u32.u64 %0, t; }" : "=r"(a) : "l"(p));
    return a;
}
__device__ __forceinline__ void ldsm4(uint32_t* r, uint32_t a) {
    asm volatile("ldmatrix.sync.aligned.m8n8.x4.shared.b16 {%0,%1,%2,%3}, [%4];"
        : "=r"(r[0]), "=r"(r[1]), "=r"(r[2]), "=r"(r[3]) : "r"(a));
}
__device__ __forceinline__ void sts32(uint32_t a, uint32_t v) {
    asm volatile("st.shared.u32 [%0], %1;" :: "r"(a), "r"(v));
}
__device__ __forceinline__ void mma16816(float* d, const uint32_t* a, uint32_t b0, uint32_t b1) {
    asm volatile("mma.sync.aligned.m16n8k16.row.col.f32.f16.f16.f32 "
        "{%0,%1,%2,%3}, {%4,%5,%6,%7}, {%8,%9}, {%0,%1,%2,%3};"
        : "+f"(d[0]), "+f"(d[1]), "+f"(d[2]), "+f"(d[3])
        : "r"(a[0]), "r"(a[1]), "r"(a[2]), "r"(a[3]), "r"(b0), "r"(b1));
}

// ---------------- layer MMA loop: software-pipelined, B direct from L2/L1 ----------------
// warp = M32 x NNTW n8-tiles; d[mh*NNTW + nt][4], mh in {0,1}
template<int NNTW>
__device__ __forceinline__ void layer_mmas(
    float (*d)[4], const uint2* __restrict__ gwl, uint32_t aAddr)
{
    uint2     B[2][NNTW];
    uint32_t  a[2][8];

    // preload kc = 0
    ldsm4(&a[0][0], aAddr);
    ldsm4(&a[0][4], aAddr + 16 * ASTRIDE);
    #pragma unroll
    for (int nt = 0; nt < NNTW; ++nt) B[0][nt] = __ldg(gwl + nt * 32);

    #pragma unroll
    for (int kc = 0; kc < NKC; ++kc) {
        const int cur = kc & 1, nxt = cur ^ 1;
        // prefetch kc+1 (A fragments + B fragments) before consuming kc
        if (kc + 1 < NKC) {
            ldsm4(&a[nxt][0], aAddr + (kc + 1) * 32);
            ldsm4(&a[nxt][4], aAddr + 16 * ASTRIDE + (kc + 1) * 32);
            const uint2* gk = gwl + (size_t)(kc + 1) * 800;
            #pragma unroll
            for (int nt = 0; nt < NNTW; ++nt) B[nxt][nt] = __ldg(gk + nt * 32);
        }
        #pragma unroll
        for (int nt = 0; nt < NNTW; ++nt) {
            mma16816(d[nt],        &a[cur][0], B[cur][nt].x, B[cur][nt].y);
            mma16816(d[NNTW + nt], &a[cur][4], B[cur][nt].x, B[cur][nt].y);
        }
    }
}

template<int NTB, int NNTW>
__device__ __forceinline__ void epi_store(
    const float (*d)[4], const float* biasL, int mg, int g, int t, uint32_t sb)
{
    #pragma unroll
    for (int mh = 0; mh < 2; ++mh) {
        const uint32_t off0 = (uint32_t)(mg * 32 + mh * 16 + g) * ASTRIDE;
        #pragma unroll
        for (int nt = 0; nt < NNTW; ++nt) {
            const float* dd = d[mh * NNTW + nt];
            int c0 = 8 * (NTB + nt) + 2 * t;
            float b0 = biasL[c0], b1 = biasL[c0 + 1];
            float v0 = fmaxf(dd[0] + b0, 0.f), v1 = fmaxf(dd[1] + b1, 0.f);
            float v2 = fmaxf(dd[2] + b0, 0.f), v3 = fmaxf(dd[3] + b1, 0.f);
            uint32_t a0 = off0 + (uint32_t)c0 * 2;
            sts32(sb + A_OFF + a0, packh2(v0, v1));
            sts32(sb + A_OFF + a0 + 8 * ASTRIDE, packh2(v2, v3));
        }
    }
}

template<int NTB, int NNTW>
__device__ __forceinline__ void epi_final(
    const float (*d)[4], const float* biasL, const float* woutS,
    float* zp, int ng, int mg, int g, int t)
{
    #pragma unroll
    for (int mh = 0; mh < 2; ++mh) {
        float z0 = 0.f, z1 = 0.f;
        #pragma unroll
        for (int nt = 0; nt < NNTW; ++nt) {
            const float* dd = d[mh * NNTW + nt];
            int c0 = 8 * (NTB + nt) + 2 * t;
            float b0 = biasL[c0], b1 = biasL[c0 + 1];
            float w0 = woutS[c0], w1 = woutS[c0 + 1];
            z0 = fmaf(fmaxf(dd[0] + b0, 0.f), w0, z0);
            z0 = fmaf(fmaxf(dd[1] + b1, 0.f), w1, z0);
            z1 = fmaf(fmaxf(dd[2] + b0, 0.f), w0, z1);
            z1 = fmaf(fmaxf(dd[3] + b1, 0.f), w1, z1);
        }
        z0 += __shfl_xor_sync(0xffffffffu, z0, 1);
        z0 += __shfl_xor_sync(0xffffffffu, z0, 2);
        z1 += __shfl_xor_sync(0xffffffffu, z1, 1);
        z1 += __shfl_xor_sync(0xffffffffu, z1, 2);
        if (t == 0) {
            int rl = mg * 32 + mh * 16 + g;
            zp[ng * TM + rl]     = z0;
            zp[ng * TM + rl + 8] = z1;
        }
    }
}

// ---------------- fused GraphConv + MLP + sigmoid ----------------
__global__ void __launch_bounds__(THREADS, 2) k_mlp(
    const float* __restrict__ x,
    const float* __restrict__ w_rel, const float* __restrict__ b_rel,
    const float* __restrict__ w_root,
    const float* __restrict__ w_in,  const float* __restrict__ b_in,
    const float* __restrict__ b_hid,
    const float* __restrict__ w_out, const float* __restrict__ b_out,
    float* __restrict__ out)
{
    extern __shared__ char smem[];
    const uint32_t sb = s2u(smem);
    const int tid  = threadIdx.x;
    const int warp = tid >> 5;
    const int lane = tid & 31;
    const int mg   = warp >> 2;        // m-group: rows mg*32 .. +31
    const int ng   = warp & 3;         // n-group: tiles {0:0-6, 1:7-12, 2:13-18, 3:19-24}
    const int g    = lane >> 2;
    const int t    = lane & 3;
    const int row0 = blockIdx.x * TM;

    float* biasS = reinterpret_cast<float*>(smem + BIAS_OFF);   // [6][200]
    float* woutS = reinterpret_cast<float*>(smem + WOUT_OFF);
    float* h0S   = reinterpret_cast<float*>(smem + H0_OFF);
    float* zp    = reinterpret_cast<float*>(smem + ZP_OFF);     // [4][64]

    // stage small vectors + h0
    if (tid < HIDDEN) woutS[tid] = __ldg(w_out + tid);
    for (int i = tid; i < NHID * HIDDEN; i += THREADS) biasS[i] = __ldg(b_hid + i);
    if (tid < TM) {
        int r = row0 + tid;
        float a  = (r < N_NODES) ? g_agg[r] : 0.0f;
        float xv = (r < N_NODES) ? __ldg(x + r) : 0.0f;
        h0S[tid] = a * __ldg(w_rel) + __ldg(b_rel) + xv * __ldg(w_root);
    }
    __syncthreads();

    // layer-1 activations (rank-1): A[r][k] = relu(h0[r]*w_in[k]+b_in[k]), k>=200 -> 0
    for (int i = tid; i < TM * 208; i += THREADS) {
        int r = i / 208, k = i - r * 208;
        float v = 0.0f;
        if (k < HIDDEN) v = fmaxf(fmaf(h0S[r], __ldg(w_in + k), __ldg(b_in + k)), 0.0f);
        *reinterpret_cast<__half*>(smem + A_OFF + r * ASTRIDE + k * 2) = __float2half_rn(v);
    }
    __syncthreads();

    // ldmatrix per-lane address (rows mg*32 .. +15; second half at +16*ASTRIDE)
    const int lrow = lane & 15;
    const uint32_t aAddr = sb + A_OFF + (mg * 32 + lrow) * ASTRIDE + (lane >> 4) * 16;

    // per-warp B base (lane-packed fragments)
    const int NTBv = (ng == 0) ? 0 : (ng == 1) ? 7 : (ng == 2) ? 13 : 19;
    const uint2* gwBase = g_wimg + NTBv * 32 + lane;

    float d[14][4];   // [2 m-halves][<=7 n-tiles][4]

    for (int l = 0; l < NHID; ++l) {
        #pragma unroll
        for (int q = 0; q < 14; ++q) {
            d[q][0] = 0.f; d[q][1] = 0.f; d[q][2] = 0.f; d[q][3] = 0.f;
        }
        const uint2* gwl = gwBase + (size_t)l * NKC * 800;

        switch (ng) {
            case 0: layer_mmas<7>(d, gwl, aAddr); break;
            case 1: layer_mmas<6>(d, gwl, aAddr); break;
            case 2: layer_mmas<6>(d, gwl, aAddr); break;
            default: layer_mmas<6>(d, gwl, aAddr); break;
        }

        const float* biasL = biasS + l * HIDDEN;
        if (l < NHID - 1) {
            __syncthreads();   // all ldsm reads of this layer's A done
            switch (ng) {
                case 0: epi_store<0, 7>(d, biasL, mg, g, t, sb); break;
                case 1: epi_store<7, 6>(d, biasL, mg, g, t, sb); break;
                case 2: epi_store<13, 6>(d, biasL, mg, g, t, sb); break;
                default: epi_store<19, 6>(d, biasL, mg, g, t, sb); break;
            }
            __syncthreads();   // new A visible before next layer's ldsm
        } else {
            switch (ng) {
                case 0: epi_final<0, 7>(d, biasL, woutS, zp, ng, mg, g, t); break;
                case 1: epi_final<7, 6>(d, biasL, woutS, zp, ng, mg, g, t); break;
                case 2: epi_final<13, 6>(d, biasL, woutS, zp, ng, mg, g, t); break;
                default: epi_final<19, 6>(d, biasL, woutS, zp, ng, mg, g, t); break;
            }
        }
    }

    __syncthreads();
    if (tid < TM) {
        int r = row0 + tid;
        if (r < N_NODES) {
            float z = zp[tid] + zp[TM + tid] + zp[2 * TM + tid] + zp[3 * TM + tid] + __ldg(b_out);
            out[r] = 1.0f / (1.0f + expf(-z));
        }
    }
}

// ---------------- launch ----------------
extern "C" void kernel_launch(void* const* d_in, const int* in_sizes, int n_in,
                              void* d_out, int out_size)
{
    const float* x      = (const float*)d_in[0];
    const int*   ei     = (const int*)d_in[1];      // int32 (jax x64 disabled)
    const float* w_rel  = (const float*)d_in[2];
    const float* b_rel  = (const float*)d_in[3];
    const float* w_root = (const float*)d_in[4];
    const float* w_in   = (const float*)d_in[5];
    const float* b_in   = (const float*)d_in[6];
    const float* w_hid  = (const float*)d_in[7];
    const float* b_hid  = (const float*)d_in[8];
    const float* w_out  = (const float*)d_in[9];
    const float* b_out  = (const float*)d_in[10];
    float*       out    = (float*)d_out;

    cudaFuncSetAttribute(k_mlp, cudaFuncAttributeMaxDynamicSharedMemorySize, SMEM_BYTES);

    k_prep<<<(NHID * NKC * 25 * 32 + 255) / 256, 256>>>(w_hid);
    k_zero<<<(N_NODES + 255) / 256, 256>>>();
    k_scatter<<<(N_EDGES / 4 + 255) / 256, 256>>>(x, ei);
    k_mlp<<<NCTA, THREADS, SMEM_BYTES>>>(
        x, w_rel, b_rel, w_root, w_in, b_in, b_hid, w_out, b_out, out);
}